// round 15
// baseline (speedup 1.0000x reference)
#include <cuda_runtime.h>
#include <cuda_fp16.h>
#include <cstdint>
#include <cstddef>

#define N_    8192
#define IND   256
#define OUTD  64
#define NS    32                 // j splits -> 2048 attention blocks
#define JSPL  (N_ / NS)          // 256 j per block
#define CH    (JSPL / 32)        // 8 chunks
#define L2E   1.4426950408889634f

// ---------------- device scratch (no runtime allocation allowed) ----------------
// g_V / g_maxkey are self-restoring (zero-init at load, re-zeroed by k_fin);
// g_S is zeroed by k_h each call.
__device__ __align__(16) uint4  g_hB4[(N_ / 16) * 128];      // B fragments uint4-paired, 1MB
__device__ __align__(16) float4 g_f2p[(N_ / 16) * 4];        // permuted f2*log2e
__device__ __align__(16) float  g_f1 [N_];
__device__ __align__(16) float  g_f1L[N_];                   // f1*log2e
__device__ __align__(16) float  g_f2 [N_];
__device__ __align__(16) float  g_V  [N_ * OUTD];
__device__ __align__(16) float  g_S  [N_];
__device__ uint32_t g_maxkey;

typedef unsigned long long ull;

// ---------------- helpers ----------------
__device__ __forceinline__ ull pk2(float x) {
    ull u; asm("mov.b64 %0, {%1, %1};" : "=l"(u) : "r"(__float_as_uint(x))); return u;
}
__device__ __forceinline__ void ffma2(ull& d, ull a, ull b) {
    asm("fma.rn.f32x2 %0, %1, %2, %0;" : "+l"(d) : "l"(a), "l"(b));
}
__device__ __forceinline__ float2 upk(ull u) {
    float2 f; asm("mov.b64 {%0, %1}, %2;" : "=f"(f.x), "=f"(f.y) : "l"(u)); return f;
}
__device__ __forceinline__ void red2(float* p, float a, float b) {
    asm volatile("red.global.add.v2.f32 [%0], {%1, %2};"
                 :: "l"(p), "f"(a), "f"(b) : "memory");
}
__device__ __forceinline__ void red1(float* p, float a) {
    asm volatile("red.global.add.f32 [%0], %1;" :: "l"(p), "f"(a) : "memory");
}
__device__ __forceinline__ void redmax(uint32_t* p, uint32_t v) {
    asm volatile("red.global.max.u32 [%0], %1;" :: "l"(p), "r"(v) : "memory");
}
__device__ __forceinline__ float ex2f(float x) {
    float r; asm("ex2.approx.f32 %0, %1;" : "=f"(r) : "f"(x)); return r;
}
__device__ __forceinline__ void mma16(float* d, const uint32_t* a, uint32_t b0, uint32_t b1) {
    asm volatile("mma.sync.aligned.m16n8k16.row.col.f32.f16.f16.f32 "
                 "{%0,%1,%2,%3}, {%4,%5,%6,%7}, {%8,%9}, {%0,%1,%2,%3};"
                 : "+f"(d[0]), "+f"(d[1]), "+f"(d[2]), "+f"(d[3])
                 : "r"(a[0]), "r"(a[1]), "r"(a[2]), "r"(a[3]), "r"(b0), "r"(b1));
}

// ---------------- launch 1: h = input@W + f1/f2 + red.max + B pack + S zero --------
// 512 blocks x 16 rows; W staged in two 128-k chunks (32KB) + in_s (16.6KB)
// -> 49.4KB smem -> 4 blocks/SM, all 512 resident in one wave.
#define KH_WS   0                       // W_s chunk: [128][64] floats (8192)
#define KH_INS  8192                    // in_s: [16][260] floats (4160)
#define KH_SMEM ((8192 + 4160) * 4)     // 49408 B
__global__ void __launch_bounds__(256, 4) k_h(const float* __restrict__ input,
                                              const float* __restrict__ W,
                                              const float* __restrict__ a) {
    extern __shared__ float sm[];
    float* W_s  = sm + KH_WS;
    float* in_s = sm + KH_INS;
    int t = threadIdx.x;
    int b = blockIdx.x;
    int rowBase = b * 16;

    // zero S for this block's 16 rows (strictly precedes k_attn's red1)
    if (t < 4)
        reinterpret_cast<float4*>(g_S)[b * 4 + t] = make_float4(0.f, 0.f, 0.f, 0.f);

    // stage input tile: 16 rows x 64 float4 = 1024 float4, 4 per thread
#pragma unroll
    for (int m = 0; m < 4; m++) {
        int idx4 = t + 256 * m;
        int r  = idx4 >> 6;
        int k4 = (idx4 & 63) * 4;
        *reinterpret_cast<float4*>(&in_s[r * 260 + k4]) =
            *reinterpret_cast<const float4*>(&input[(size_t)(rowBase + r) * IND + k4]);
    }

    const int row = t >> 4;      // 0..15
    const int tx  = t & 15;      // cols 4tx..4tx+3
    ull acc0 = 0ull, acc1 = 0ull;

#pragma unroll
    for (int ch = 0; ch < 2; ch++) {
        __syncthreads();
        // stage W chunk: k in [128ch, 128ch+128): 128 x 16 float4, 8 per thread
#pragma unroll
        for (int m = 0; m < 8; m++) {
            int idx4 = t + 256 * m;          // 0..2047
            *reinterpret_cast<float4*>(&W_s[4 * idx4]) =
                *reinterpret_cast<const float4*>(&W[128 * 64 * ch + 4 * idx4]);
        }
        __syncthreads();

        const float* ir = &in_s[row * 260 + 128 * ch];
#pragma unroll 8
        for (int k = 0; k < 128; k++) {
            ulonglong2 wv = *reinterpret_cast<const ulonglong2*>(&W_s[k * 64 + 4 * tx]);
            ull iv = pk2(ir[k]);
            ffma2(acc0, iv, wv.x);
            ffma2(acc1, iv, wv.y);
        }
    }

    float2 p0 = upk(acc0), p1 = upk(acc1);

    // fused f1/f2 partials over this thread's 4 cols, reduce over 16 lanes
    {
        float4 A1 = *reinterpret_cast<const float4*>(&a[4 * tx]);
        float4 A2 = *reinterpret_cast<const float4*>(&a[OUTD + 4 * tx]);
        float s1 = p0.x * A1.x + p0.y * A1.y + p1.x * A1.z + p1.y * A1.w;
        float s2 = p0.x * A2.x + p0.y * A2.y + p1.x * A2.z + p1.y * A2.w;
#pragma unroll
        for (int off = 1; off < 16; off <<= 1) {
            s1 += __shfl_xor_sync(0xFFFFFFFFu, s1, off);
            s2 += __shfl_xor_sync(0xFFFFFFFFu, s2, off);
        }
        if (tx == 0) {
            int grow = rowBase + row;
            g_f1[grow]  = s1;
            g_f1L[grow] = s1 * L2E;
            g_f2[grow]  = s2;
            uint32_t u = __float_as_uint(s2);
            uint32_t key = u ^ (uint32_t)(((int)u >> 31) | 0x80000000);
            redmax(&g_maxkey, key);
        }
    }

    // reuse smem for the pack: tile[16][65] + f2s[16]
    float* tile = sm;             // 1040 floats
    float* f2s  = sm + 1100;
    __syncthreads();              // all W_s/in_s reads done

    tile[row * 65 + 4 * tx]     = p0.x;
    tile[row * 65 + 4 * tx + 1] = p0.y;
    tile[row * 65 + 4 * tx + 2] = p1.x;
    tile[row * 65 + 4 * tx + 3] = p1.y;
    if (tx == 0) f2s[row] = g_f2[rowBase + row] * L2E;   // just computed by lane 0 path
    __syncthreads();

    // f2p (permuted): fc = 0..3
    if (t < 4) {
        int j = 4 * t;
        g_f2p[b * 4 + t] = make_float4(f2s[j], f2s[j + 1], f2s[j + 2], f2s[j + 3]);
    }

    // pack B fragments (permuted, uint4 pairs q/q+4); 128 work items
    if (t < 128) {
        int qq   = t >> 5;
        int lane = t & 31;
        int fr = lane >> 2, fc = lane & 3;
        int j0 = 4 * fc;
        int n1 = qq * 8 + fr;
        int n2 = (qq + 4) * 8 + fr;
        __half2 lo1 = __floats2half2_rn(tile[j0 * 65 + n1],       tile[(j0 + 1) * 65 + n1]);
        __half2 hi1 = __floats2half2_rn(tile[(j0 + 2) * 65 + n1], tile[(j0 + 3) * 65 + n1]);
        __half2 lo2 = __floats2half2_rn(tile[j0 * 65 + n2],       tile[(j0 + 1) * 65 + n2]);
        __half2 hi2 = __floats2half2_rn(tile[(j0 + 2) * 65 + n2], tile[(j0 + 3) * 65 + n2]);
        uint4 pkt;
        pkt.x = *reinterpret_cast<uint32_t*>(&lo1);
        pkt.y = *reinterpret_cast<uint32_t*>(&hi1);
        pkt.z = *reinterpret_cast<uint32_t*>(&lo2);
        pkt.w = *reinterpret_cast<uint32_t*>(&hi2);
        g_hB4[(b * 4 + qq) * 32 + lane] = pkt;
    }
}

// ---------------- launch 2: smem-B register-fragment attention (unchanged) ----------------
__global__ void __launch_bounds__(256, 3) k_attn(const int* __restrict__ adj) {
    __shared__ uint4  sB[2048];   // 32KB B fragments for this block's 256 j
    __shared__ float4 sF[64];     // 1KB  f2p

    int t = threadIdx.x;
    int wid = t >> 5, lane = t & 31;
    int fr = lane >> 2, fc = lane & 3;
    int mrow   = blockIdx.y * 128 + wid * 16;
    int jStart = blockIdx.x * JSPL;

    {
        const uint4* gB = g_hB4 + (size_t)(jStart / 16) * 128;
#pragma unroll
        for (int m = 0; m < 8; m++) sB[t + 256 * m] = gB[t + 256 * m];
        if (t < 64) sF[t] = g_f2p[(size_t)(jStart / 16) * 4 + t];
    }

    float mL;
    {
        uint32_t k = g_maxkey;
        uint32_t u = (k & 0x80000000u) ? (k ^ 0x80000000u) : ~k;
        mL = __uint_as_float(u) * L2E;
    }

    float f1L0 = g_f1L[mrow + fr];
    float f1L1 = g_f1L[mrow + fr + 8];
    float y0 = f1L0 + mL, y1 = f1L1 + mL;
    float ci0 = fmaxf(y0, 0.01f * y0);
    float ci1 = fmaxf(y1, 0.01f * y1);

    const int4* pr0 = reinterpret_cast<const int4*>(adj + (size_t)(mrow + fr) * N_ + jStart) + fc;
    const int4* pr1 = reinterpret_cast<const int4*>(adj + (size_t)(mrow + fr + 8) * N_ + jStart) + fc;

    float accv[8][4];
#pragma unroll
    for (int q = 0; q < 8; q++)
#pragma unroll
        for (int g = 0; g < 4; g++) accv[q][g] = 0.f;
    float accs[4] = {0.f, 0.f, 0.f, 0.f};

    const uint32_t bone = (fr == 0) ? 0x3C003C00u : 0u;

    int4 avA0 = __ldcs(pr0), avA1 = __ldcs(pr1);
    __syncthreads();

#define GEN_A(AREG, AVA, AVB, FV)                                                 \
    do {                                                                          \
        float e00, e01, e02, e03, e10, e11, e12, e13;                             \
        { float y = f1L0 + (FV).x; e00 = ex2f(fmaxf(y - ci0, fmaf(y, 0.01f, -ci0))); } \
        { float y = f1L0 + (FV).y; e01 = ex2f(fmaxf(y - ci0, fmaf(y, 0.01f, -ci0))); } \
        { float y = f1L0 + (FV).z; e02 = ex2f(fmaxf(y - ci0, fmaf(y, 0.01f, -ci0))); } \
        { float y = f1L0 + (FV).w; e03 = ex2f(fmaxf(y - ci0, fmaf(y, 0.01f, -ci0))); } \
        { float y = f1L1 + (FV).x; e10 = ex2f(fmaxf(y - ci1, fmaf(y, 0.01f, -ci1))); } \
        { float y = f1L1 + (FV).y; e11 = ex2f(fmaxf(y - ci1, fmaf(y, 0.01f, -ci1))); } \
        { float y = f1L1 + (FV).z; e12 = ex2f(fmaxf(y - ci1, fmaf(y, 0.01f, -ci1))); } \
        { float y = f1L1 + (FV).w; e13 = ex2f(fmaxf(y - ci1, fmaf(y, 0.01f, -ci1))); } \
        __half2 h0 = __floats2half2_rn(e00, e01);                                 \
        __half2 h1 = __floats2half2_rn(e10, e11);                                 \
        __half2 h2 = __floats2half2_rn(e02, e03);                                 \
        __half2 h3 = __floats2half2_rn(e12, e13);                                 \
        uint32_t mA0 = (uint32_t)(AVA).x * 0xFFFFu + (uint32_t)(AVA).y * 0xFFFF0000u; \
        uint32_t mA1 = (uint32_t)(AVA).z * 0xFFFFu + (uint32_t)(AVA).w * 0xFFFF0000u; \
        uint32_t mB0 = (uint32_t)(AVB).x * 0xFFFFu + (uint32_t)(AVB).y * 0xFFFF0000u; \
        uint32_t mB1 = (uint32_t)(AVB).z * 0xFFFFu + (uint32_t)(AVB).w * 0xFFFF0000u; \
        (AREG)[0] = *reinterpret_cast<uint32_t*>(&h0) & mA0;                      \
        (AREG)[1] = *reinterpret_cast<uint32_t*>(&h1) & mB0;                      \
        (AREG)[2] = *reinterpret_cast<uint32_t*>(&h2) & mA1;                      \
        (AREG)[3] = *reinterpret_cast<uint32_t*>(&h3) & mB1;                      \
    } while (0)

#pragma unroll 2
    for (int ch = 0; ch < CH; ch++) {
        int4 avB0 = __ldcs(pr0 + 4), avB1 = __ldcs(pr1 + 4);

        {
            uint4 bq[4];
#pragma unroll
            for (int qq = 0; qq < 4; qq++) bq[qq] = sB[ch * 256 + qq * 32 + lane];
            float4 fv = sF[ch * 8 + fc];
            uint32_t a[4];
            GEN_A(a, avA0, avA1, fv);
#pragma unroll
            for (int qq = 0; qq < 4; qq++) {
                mma16(accv[qq],     a, bq[qq].x, bq[qq].y);
                mma16(accv[qq + 4], a, bq[qq].z, bq[qq].w);
            }
            mma16(accs, a, bone, bone);
        }

        if (ch + 1 < CH) { avA0 = __ldcs(pr0 + 8); avA1 = __ldcs(pr1 + 8); }

        {
            uint4 bq[4];
#pragma unroll
            for (int qq = 0; qq < 4; qq++) bq[qq] = sB[ch * 256 + 128 + qq * 32 + lane];
            float4 fv = sF[ch * 8 + 4 + fc];
            uint32_t a[4];
            GEN_A(a, avB0, avB1, fv);
#pragma unroll
            for (int qq = 0; qq < 4; qq++) {
                mma16(accv[qq],     a, bq[qq].x, bq[qq].y);
                mma16(accv[qq + 4], a, bq[qq].z, bq[qq].w);
            }
            mma16(accs, a, bone, bone);
        }

        pr0 += 8; pr1 += 8;
    }
#undef GEN_A

#pragma unroll
    for (int q = 0; q < 8; q++) {
        int col = q * 8 + 2 * fc;
        red2(&g_V[(mrow + fr) * OUTD + col],     accv[q][0], accv[q][1]);
        red2(&g_V[(mrow + fr + 8) * OUTD + col], accv[q][2], accv[q][3]);
    }
    if (fc == 0) {
        red1(&g_S[mrow + fr],     accs[0]);
        red1(&g_S[mrow + fr + 8], accs[2]);
    }
}

// ---------------- launch 3: normalize + scalar outputs + state restore ----------------
__global__ void __launch_bounds__(256) k_fin(float* __restrict__ out) {
    int gid = blockIdx.x * blockDim.x + threadIdx.x;   // 0..131071 float4s
    float4 v = reinterpret_cast<const float4*>(g_V)[gid];
    float  s = g_S[gid >> 4];
    float  inv = 1.0f / s;
    reinterpret_cast<float4*>(out)[gid] =
        make_float4(v.x * inv, v.y * inv, v.z * inv, v.w * inv);
    reinterpret_cast<float4*>(g_V)[gid] = make_float4(0.f, 0.f, 0.f, 0.f);
    if (gid < 3) {
        float x;
        if (gid == 0)      x = g_f1[1] + g_f2[2];   // face_Rhand = e[1,2]
        else if (gid == 1) x = g_f1[1] + g_f2[3];   // face_Lhand = e[1,3]
        else               x = g_f1[3] + g_f2[2];   // Rhand_Lhand = e[3,2]
        out[N_ * OUTD + gid] = fmaxf(x, 0.01f * x);
    }
    if (gid == 4) g_maxkey = 0u;
}

// ---------------- launch ----------------
extern "C" void kernel_launch(void* const* d_in, const int* in_sizes, int n_in,
                              void* d_out, int out_size) {
    const float* input = (const float*)d_in[0];
    const int*   adj   = (const int*)  d_in[1];
    const float* W     = (const float*)d_in[2];
    const float* a     = (const float*)d_in[3];
    float*       out   = (float*)d_out;
    (void)in_sizes; (void)n_in; (void)out_size;

    cudaFuncSetAttribute(k_h, cudaFuncAttributeMaxDynamicSharedMemorySize, KH_SMEM);

    k_h   <<<512, 256, KH_SMEM>>>(input, W, a);
    k_attn<<<dim3(NS, N_ / 128), 256>>>(adj);
    k_fin <<<512, 256>>>(out);
}

// round 16
// speedup vs baseline: 1.0336x; 1.0336x over previous
#include <cuda_runtime.h>
#include <cuda_fp16.h>
#include <cstdint>
#include <cstddef>

#define N_    8192
#define IND   256
#define OUTD  64
#define NS    32                 // j splits -> 2048 attention blocks
#define JSPL  (N_ / NS)          // 256 j per block
#define CH    (JSPL / 32)        // 8 chunks
#define L2E   1.4426950408889634f

// ---------------- device scratch (no runtime allocation allowed) ----------------
// g_V / g_maxkey are self-restoring (zero-init at load, re-zeroed by k_fin);
// g_S is zeroed by k_h each call.
__device__ __align__(16) uint4  g_hB4[(N_ / 16) * 128];      // B fragments uint4-paired, 1MB
__device__ __align__(16) float4 g_f2p[(N_ / 16) * 4];        // permuted f2*log2e
__device__ __align__(16) float  g_f1 [N_];
__device__ __align__(16) float  g_f1L[N_];                   // f1*log2e
__device__ __align__(16) float  g_f2 [N_];
__device__ __align__(16) float  g_V  [N_ * OUTD];
__device__ __align__(16) float  g_S  [N_];
__device__ uint32_t g_maxkey;

typedef unsigned long long ull;

// ---------------- helpers ----------------
__device__ __forceinline__ ull pk2(float x) {
    ull u; asm("mov.b64 %0, {%1, %1};" : "=l"(u) : "r"(__float_as_uint(x))); return u;
}
__device__ __forceinline__ void ffma2(ull& d, ull a, ull b) {
    asm("fma.rn.f32x2 %0, %1, %2, %0;" : "+l"(d) : "l"(a), "l"(b));
}
__device__ __forceinline__ float2 upk(ull u) {
    float2 f; asm("mov.b64 {%0, %1}, %2;" : "=f"(f.x), "=f"(f.y) : "l"(u)); return f;
}
__device__ __forceinline__ void red2(float* p, float a, float b) {
    asm volatile("red.global.add.v2.f32 [%0], {%1, %2};"
                 :: "l"(p), "f"(a), "f"(b) : "memory");
}
__device__ __forceinline__ void red1(float* p, float a) {
    asm volatile("red.global.add.f32 [%0], %1;" :: "l"(p), "f"(a) : "memory");
}
__device__ __forceinline__ void redmax(uint32_t* p, uint32_t v) {
    asm volatile("red.global.max.u32 [%0], %1;" :: "l"(p), "r"(v) : "memory");
}
__device__ __forceinline__ float ex2f(float x) {
    float r; asm("ex2.approx.f32 %0, %1;" : "=f"(r) : "f"(x)); return r;
}
__device__ __forceinline__ void mma16(float* d, const uint32_t* a, uint32_t b0, uint32_t b1) {
    asm volatile("mma.sync.aligned.m16n8k16.row.col.f32.f16.f16.f32 "
                 "{%0,%1,%2,%3}, {%4,%5,%6,%7}, {%8,%9}, {%0,%1,%2,%3};"
                 : "+f"(d[0]), "+f"(d[1]), "+f"(d[2]), "+f"(d[3])
                 : "r"(a[0]), "r"(a[1]), "r"(a[2]), "r"(a[3]), "r"(b0), "r"(b1));
}

// ---------------- launch 1: h = input@W + f1/f2 + red.max + B pack + S zero --------
// 256 blocks x 32 rows; thread tile 1 row x 8 cols; W staged in two 128-k chunks.
// smem 65.3KB -> 2 blocks/SM, all 256 blocks resident in one wave (16 warps/SM).
#define KH_WS   0                       // W_s chunk: [128][64] floats (8192)
#define KH_INS  8192                    // in_s: [32][260] floats (8320)
#define KH_SMEM ((8192 + 8320) * 4)     // 66048 B
__global__ void __launch_bounds__(256) k_h(const float* __restrict__ input,
                                           const float* __restrict__ W,
                                           const float* __restrict__ a) {
    extern __shared__ float sm[];
    float* W_s  = sm + KH_WS;
    float* in_s = sm + KH_INS;
    int t = threadIdx.x;
    int b = blockIdx.x;
    int rowBase = b * 32;

    // zero S for this block's 32 rows (strictly precedes k_attn's red1)
    if (t < 8)
        reinterpret_cast<float4*>(g_S)[b * 8 + t] = make_float4(0.f, 0.f, 0.f, 0.f);

    // stage input tile: 32 rows x 64 float4 = 2048 float4, 8 per thread
#pragma unroll
    for (int m = 0; m < 8; m++) {
        int idx4 = t + 256 * m;
        int r  = idx4 >> 6;
        int k4 = (idx4 & 63) * 4;
        *reinterpret_cast<float4*>(&in_s[r * 260 + k4]) =
            *reinterpret_cast<const float4*>(&input[(size_t)(rowBase + r) * IND + k4]);
    }

    const int row = t >> 3;      // 0..31
    const int tx  = t & 7;       // cols {4tx..4tx+3} and {32+4tx..35+4tx}
    ull acc[4] = {0ull, 0ull, 0ull, 0ull};

#pragma unroll
    for (int ch = 0; ch < 2; ch++) {
        __syncthreads();
        // stage W chunk: k in [128ch, 128ch+128): 2048 float4, 8 per thread
#pragma unroll
        for (int m = 0; m < 8; m++) {
            int idx4 = t + 256 * m;
            *reinterpret_cast<float4*>(&W_s[4 * idx4]) =
                *reinterpret_cast<const float4*>(&W[128 * 64 * ch + 4 * idx4]);
        }
        __syncthreads();

        const float* ir = &in_s[row * 260 + 128 * ch];
#pragma unroll 8
        for (int k = 0; k < 128; k++) {
            ulonglong2 wa = *reinterpret_cast<const ulonglong2*>(&W_s[k * 64 + 4 * tx]);
            ulonglong2 wb = *reinterpret_cast<const ulonglong2*>(&W_s[k * 64 + 32 + 4 * tx]);
            ull iv = pk2(ir[k]);
            ffma2(acc[0], iv, wa.x);
            ffma2(acc[1], iv, wa.y);
            ffma2(acc[2], iv, wb.x);
            ffma2(acc[3], iv, wb.y);
        }
    }

    float2 p0 = upk(acc[0]), p1 = upk(acc[1]);
    float2 p2 = upk(acc[2]), p3 = upk(acc[3]);

    // fused f1/f2 partials over this thread's 8 cols, reduce over 8 lanes
    float s2r = 0.f;
    {
        float4 A1a = *reinterpret_cast<const float4*>(&a[4 * tx]);
        float4 A1b = *reinterpret_cast<const float4*>(&a[32 + 4 * tx]);
        float4 A2a = *reinterpret_cast<const float4*>(&a[OUTD + 4 * tx]);
        float4 A2b = *reinterpret_cast<const float4*>(&a[OUTD + 32 + 4 * tx]);
        float s1 = p0.x * A1a.x + p0.y * A1a.y + p1.x * A1a.z + p1.y * A1a.w
                 + p2.x * A1b.x + p2.y * A1b.y + p3.x * A1b.z + p3.y * A1b.w;
        float s2 = p0.x * A2a.x + p0.y * A2a.y + p1.x * A2a.z + p1.y * A2a.w
                 + p2.x * A2b.x + p2.y * A2b.y + p3.x * A2b.z + p3.y * A2b.w;
#pragma unroll
        for (int off = 1; off < 8; off <<= 1) {
            s1 += __shfl_xor_sync(0xFFFFFFFFu, s1, off);
            s2 += __shfl_xor_sync(0xFFFFFFFFu, s2, off);
        }
        s2r = s2;
        if (tx == 0) {
            int grow = rowBase + row;
            g_f1[grow]  = s1;
            g_f1L[grow] = s1 * L2E;
            g_f2[grow]  = s2;
            uint32_t u = __float_as_uint(s2);
            uint32_t key = u ^ (uint32_t)(((int)u >> 31) | 0x80000000);
            redmax(&g_maxkey, key);
        }
    }

    // reuse smem for the pack: tile[32][65] + f2s[32]
    float* tile = sm;             // 2080 floats
    float* f2s  = sm + 2112;
    __syncthreads();              // all W_s/in_s reads done

    {
        float* tr = &tile[row * 65];
        tr[4 * tx]     = p0.x; tr[4 * tx + 1] = p0.y;
        tr[4 * tx + 2] = p1.x; tr[4 * tx + 3] = p1.y;
        tr[32 + 4 * tx]     = p2.x; tr[32 + 4 * tx + 1] = p2.y;
        tr[32 + 4 * tx + 2] = p3.x; tr[32 + 4 * tx + 3] = p3.y;
        if (tx == 0) f2s[row] = s2r * L2E;
    }
    __syncthreads();

    // f2p (permuted): 8 items = 2 j16 groups x 4 fc
    if (t < 8) {
        int j16r = t >> 2, fc = t & 3;
        int j = j16r * 16 + 4 * fc;
        g_f2p[(b * 2 + j16r) * 4 + fc] =
            make_float4(f2s[j], f2s[j + 1], f2s[j + 2], f2s[j + 3]);
    }

    // pack B fragments (permuted, uint4 pairs q/q+4): 256 items, 1 per thread
    {
        int j16r = t >> 7;            // 0..1
        int qq   = (t >> 5) & 3;      // 0..3
        int lane = t & 31;
        int fr = lane >> 2, fc = lane & 3;
        int j0 = j16r * 16 + 4 * fc;
        int n1 = qq * 8 + fr;
        int n2 = (qq + 4) * 8 + fr;
        __half2 lo1 = __floats2half2_rn(tile[j0 * 65 + n1],       tile[(j0 + 1) * 65 + n1]);
        __half2 hi1 = __floats2half2_rn(tile[(j0 + 2) * 65 + n1], tile[(j0 + 3) * 65 + n1]);
        __half2 lo2 = __floats2half2_rn(tile[j0 * 65 + n2],       tile[(j0 + 1) * 65 + n2]);
        __half2 hi2 = __floats2half2_rn(tile[(j0 + 2) * 65 + n2], tile[(j0 + 3) * 65 + n2]);
        uint4 pkt;
        pkt.x = *reinterpret_cast<uint32_t*>(&lo1);
        pkt.y = *reinterpret_cast<uint32_t*>(&hi1);
        pkt.z = *reinterpret_cast<uint32_t*>(&lo2);
        pkt.w = *reinterpret_cast<uint32_t*>(&hi2);
        g_hB4[((b * 2 + j16r) * 4 + qq) * 32 + lane] = pkt;
    }
}

// ---------------- launch 2: smem-B register-fragment attention (unchanged) ----------------
__global__ void __launch_bounds__(256, 3) k_attn(const int* __restrict__ adj) {
    __shared__ uint4  sB[2048];   // 32KB B fragments for this block's 256 j
    __shared__ float4 sF[64];     // 1KB  f2p

    int t = threadIdx.x;
    int wid = t >> 5, lane = t & 31;
    int fr = lane >> 2, fc = lane & 3;
    int mrow   = blockIdx.y * 128 + wid * 16;
    int jStart = blockIdx.x * JSPL;

    {
        const uint4* gB = g_hB4 + (size_t)(jStart / 16) * 128;
#pragma unroll
        for (int m = 0; m < 8; m++) sB[t + 256 * m] = gB[t + 256 * m];
        if (t < 64) sF[t] = g_f2p[(size_t)(jStart / 16) * 4 + t];
    }

    float mL;
    {
        uint32_t k = g_maxkey;
        uint32_t u = (k & 0x80000000u) ? (k ^ 0x80000000u) : ~k;
        mL = __uint_as_float(u) * L2E;
    }

    float f1L0 = g_f1L[mrow + fr];
    float f1L1 = g_f1L[mrow + fr + 8];
    float y0 = f1L0 + mL, y1 = f1L1 + mL;
    float ci0 = fmaxf(y0, 0.01f * y0);
    float ci1 = fmaxf(y1, 0.01f * y1);

    const int4* pr0 = reinterpret_cast<const int4*>(adj + (size_t)(mrow + fr) * N_ + jStart) + fc;
    const int4* pr1 = reinterpret_cast<const int4*>(adj + (size_t)(mrow + fr + 8) * N_ + jStart) + fc;

    float accv[8][4];
#pragma unroll
    for (int q = 0; q < 8; q++)
#pragma unroll
        for (int g = 0; g < 4; g++) accv[q][g] = 0.f;
    float accs[4] = {0.f, 0.f, 0.f, 0.f};

    const uint32_t bone = (fr == 0) ? 0x3C003C00u : 0u;

    int4 avA0 = __ldcs(pr0), avA1 = __ldcs(pr1);
    __syncthreads();

#define GEN_A(AREG, AVA, AVB, FV)                                                 \
    do {                                                                          \
        float e00, e01, e02, e03, e10, e11, e12, e13;                             \
        { float y = f1L0 + (FV).x; e00 = ex2f(fmaxf(y - ci0, fmaf(y, 0.01f, -ci0))); } \
        { float y = f1L0 + (FV).y; e01 = ex2f(fmaxf(y - ci0, fmaf(y, 0.01f, -ci0))); } \
        { float y = f1L0 + (FV).z; e02 = ex2f(fmaxf(y - ci0, fmaf(y, 0.01f, -ci0))); } \
        { float y = f1L0 + (FV).w; e03 = ex2f(fmaxf(y - ci0, fmaf(y, 0.01f, -ci0))); } \
        { float y = f1L1 + (FV).x; e10 = ex2f(fmaxf(y - ci1, fmaf(y, 0.01f, -ci1))); } \
        { float y = f1L1 + (FV).y; e11 = ex2f(fmaxf(y - ci1, fmaf(y, 0.01f, -ci1))); } \
        { float y = f1L1 + (FV).z; e12 = ex2f(fmaxf(y - ci1, fmaf(y, 0.01f, -ci1))); } \
        { float y = f1L1 + (FV).w; e13 = ex2f(fmaxf(y - ci1, fmaf(y, 0.01f, -ci1))); } \
        __half2 h0 = __floats2half2_rn(e00, e01);                                 \
        __half2 h1 = __floats2half2_rn(e10, e11);                                 \
        __half2 h2 = __floats2half2_rn(e02, e03);                                 \
        __half2 h3 = __floats2half2_rn(e12, e13);                                 \
        uint32_t mA0 = (uint32_t)(AVA).x * 0xFFFFu + (uint32_t)(AVA).y * 0xFFFF0000u; \
        uint32_t mA1 = (uint32_t)(AVA).z * 0xFFFFu + (uint32_t)(AVA).w * 0xFFFF0000u; \
        uint32_t mB0 = (uint32_t)(AVB).x * 0xFFFFu + (uint32_t)(AVB).y * 0xFFFF0000u; \
        uint32_t mB1 = (uint32_t)(AVB).z * 0xFFFFu + (uint32_t)(AVB).w * 0xFFFF0000u; \
        (AREG)[0] = *reinterpret_cast<uint32_t*>(&h0) & mA0;                      \
        (AREG)[1] = *reinterpret_cast<uint32_t*>(&h1) & mB0;                      \
        (AREG)[2] = *reinterpret_cast<uint32_t*>(&h2) & mA1;                      \
        (AREG)[3] = *reinterpret_cast<uint32_t*>(&h3) & mB1;                      \
    } while (0)

#pragma unroll 2
    for (int ch = 0; ch < CH; ch++) {
        int4 avB0 = __ldcs(pr0 + 4), avB1 = __ldcs(pr1 + 4);

        {
            uint4 bq[4];
#pragma unroll
            for (int qq = 0; qq < 4; qq++) bq[qq] = sB[ch * 256 + qq * 32 + lane];
            float4 fv = sF[ch * 8 + fc];
            uint32_t a[4];
            GEN_A(a, avA0, avA1, fv);
#pragma unroll
            for (int qq = 0; qq < 4; qq++) {
                mma16(accv[qq],     a, bq[qq].x, bq[qq].y);
                mma16(accv[qq + 4], a, bq[qq].z, bq[qq].w);
            }
            mma16(accs, a, bone, bone);
        }

        if (ch + 1 < CH) { avA0 = __ldcs(pr0 + 8); avA1 = __ldcs(pr1 + 8); }

        {
            uint4 bq[4];
#pragma unroll
            for (int qq = 0; qq < 4; qq++) bq[qq] = sB[ch * 256 + 128 + qq * 32 + lane];
            float4 fv = sF[ch * 8 + 4 + fc];
            uint32_t a[4];
            GEN_A(a, avB0, avB1, fv);
#pragma unroll
            for (int qq = 0; qq < 4; qq++) {
                mma16(accv[qq],     a, bq[qq].x, bq[qq].y);
                mma16(accv[qq + 4], a, bq[qq].z, bq[qq].w);
            }
            mma16(accs, a, bone, bone);
        }

        pr0 += 8; pr1 += 8;
    }
#undef GEN_A

#pragma unroll
    for (int q = 0; q < 8; q++) {
        int col = q * 8 + 2 * fc;
        red2(&g_V[(mrow + fr) * OUTD + col],     accv[q][0], accv[q][1]);
        red2(&g_V[(mrow + fr + 8) * OUTD + col], accv[q][2], accv[q][3]);
    }
    if (fc == 0) {
        red1(&g_S[mrow + fr],     accs[0]);
        red1(&g_S[mrow + fr + 8], accs[2]);
    }
}

// ---------------- launch 3: normalize + scalar outputs + state restore ----------------
__global__ void __launch_bounds__(256) k_fin(float* __restrict__ out) {
    int gid = blockIdx.x * blockDim.x + threadIdx.x;   // 0..131071 float4s
    float4 v = reinterpret_cast<const float4*>(g_V)[gid];
    float  s = g_S[gid >> 4];
    float  inv = 1.0f / s;
    reinterpret_cast<float4*>(out)[gid] =
        make_float4(v.x * inv, v.y * inv, v.z * inv, v.w * inv);
    reinterpret_cast<float4*>(g_V)[gid] = make_float4(0.f, 0.f, 0.f, 0.f);
    if (gid < 3) {
        float x;
        if (gid == 0)      x = g_f1[1] + g_f2[2];   // face_Rhand = e[1,2]
        else if (gid == 1) x = g_f1[1] + g_f2[3];   // face_Lhand = e[1,3]
        else               x = g_f1[3] + g_f2[2];   // Rhand_Lhand = e[3,2]
        out[N_ * OUTD + gid] = fmaxf(x, 0.01f * x);
    }
    if (gid == 4) g_maxkey = 0u;
}

// ---------------- launch ----------------
extern "C" void kernel_launch(void* const* d_in, const int* in_sizes, int n_in,
                              void* d_out, int out_size) {
    const float* input = (const float*)d_in[0];
    const int*   adj   = (const int*)  d_in[1];
    const float* W     = (const float*)d_in[2];
    const float* a     = (const float*)d_in[3];
    float*       out   = (float*)d_out;
    (void)in_sizes; (void)n_in; (void)out_size;

    cudaFuncSetAttribute(k_h, cudaFuncAttributeMaxDynamicSharedMemorySize, KH_SMEM);

    k_h   <<<256, 256, KH_SMEM>>>(input, W, a);
    k_attn<<<dim3(NS, N_ / 128), 256>>>(adj);
    k_fin <<<512, 256>>>(out);
}

// round 17
// speedup vs baseline: 1.0777x; 1.0426x over previous
#include <cuda_runtime.h>
#include <cuda_fp16.h>
#include <cstdint>
#include <cstddef>

#define N_    8192
#define IND   256
#define OUTD  64
#define NS    32                 // j splits -> 2048 attention blocks
#define JSPL  (N_ / NS)          // 256 j per block
#define CH    (JSPL / 32)        // 8 chunks
#define L2E   1.4426950408889634f

// ---------------- device scratch (no runtime allocation allowed) ----------------
// g_V / g_maxkey are self-restoring (zero-init at load, re-zeroed by k_fin);
// g_S is zeroed by k_h each call.
__device__ __align__(16) uint4  g_hB4[(N_ / 16) * 128];      // B fragments uint4-paired, 1MB
__device__ __align__(16) float4 g_f2p[(N_ / 16) * 4];        // permuted f2*log2e
__device__ __align__(16) float  g_f1 [N_];
__device__ __align__(16) float  g_f1L[N_];                   // f1*log2e
__device__ __align__(16) float  g_f2 [N_];
__device__ __align__(16) float  g_V  [N_ * OUTD];
__device__ __align__(16) float  g_S  [N_];
__device__ uint32_t g_maxkey;

typedef unsigned long long ull;

// ---------------- helpers ----------------
__device__ __forceinline__ ull pk2(float x) {
    ull u; asm("mov.b64 %0, {%1, %1};" : "=l"(u) : "r"(__float_as_uint(x))); return u;
}
__device__ __forceinline__ void ffma2(ull& d, ull a, ull b) {
    asm("fma.rn.f32x2 %0, %1, %2, %0;" : "+l"(d) : "l"(a), "l"(b));
}
__device__ __forceinline__ float2 upk(ull u) {
    float2 f; asm("mov.b64 {%0, %1}, %2;" : "=f"(f.x), "=f"(f.y) : "l"(u)); return f;
}
__device__ __forceinline__ void red2(float* p, float a, float b) {
    asm volatile("red.global.add.v2.f32 [%0], {%1, %2};"
                 :: "l"(p), "f"(a), "f"(b) : "memory");
}
__device__ __forceinline__ void red1(float* p, float a) {
    asm volatile("red.global.add.f32 [%0], %1;" :: "l"(p), "f"(a) : "memory");
}
__device__ __forceinline__ void redmax(uint32_t* p, uint32_t v) {
    asm volatile("red.global.max.u32 [%0], %1;" :: "l"(p), "r"(v) : "memory");
}
__device__ __forceinline__ float ex2f(float x) {
    float r; asm("ex2.approx.f32 %0, %1;" : "=f"(r) : "f"(x)); return r;
}
__device__ __forceinline__ void mma16(float* d, const uint32_t* a, uint32_t b0, uint32_t b1) {
    asm volatile("mma.sync.aligned.m16n8k16.row.col.f32.f16.f16.f32 "
                 "{%0,%1,%2,%3}, {%4,%5,%6,%7}, {%8,%9}, {%0,%1,%2,%3};"
                 : "+f"(d[0]), "+f"(d[1]), "+f"(d[2]), "+f"(d[3])
                 : "r"(a[0]), "r"(a[1]), "r"(a[2]), "r"(a[3]), "r"(b0), "r"(b1));
}

// ---------------- launch 1: h = input@W + f1/f2 + red.max + B pack + S zero --------
// 256 blocks x 128 threads x 32 rows; thread tile 2 rows x 8 cols (8 FFMA2/k).
// No input staging (broadcast GMEM float4 reads); W k-chunked in ONE 32KB buffer.
#define KH_SMEM (8192 * 4)              // 32768 B: W_s chunk [128][64]
__global__ void __launch_bounds__(128) k_h(const float* __restrict__ input,
                                           const float* __restrict__ W,
                                           const float* __restrict__ a) {
    extern __shared__ float sm[];
    float* W_s = sm;
    int t = threadIdx.x;
    int b = blockIdx.x;
    int rowBase = b * 32;

    // zero S for this block's 32 rows (strictly precedes k_attn's red1)
    if (t < 8)
        reinterpret_cast<float4*>(g_S)[b * 8 + t] = make_float4(0.f, 0.f, 0.f, 0.f);

    const int rp  = t >> 3;      // 0..15 -> rows 2rp, 2rp+1
    const int tx  = t & 7;       // cols {4tx..4tx+3} and {32+4tx..35+4tx}
    const float* ir0 = input + (size_t)(rowBase + 2 * rp) * IND;
    const float* ir1 = ir0 + IND;

    ull acc[2][4];
#pragma unroll
    for (int r = 0; r < 2; r++)
#pragma unroll
        for (int g = 0; g < 4; g++) acc[r][g] = 0ull;

#pragma unroll
    for (int ch = 0; ch < 2; ch++) {
        __syncthreads();
        // stage W chunk: k in [128ch, 128ch+128): 2048 float4, 16 per thread
#pragma unroll
        for (int m = 0; m < 16; m++) {
            int idx4 = t + 128 * m;
            *reinterpret_cast<float4*>(&W_s[4 * idx4]) =
                *reinterpret_cast<const float4*>(&W[128 * 64 * ch + 4 * idx4]);
        }
        __syncthreads();

#pragma unroll 4
        for (int kb = 0; kb < 128; kb += 4) {
            float4 iv0 = *reinterpret_cast<const float4*>(&ir0[128 * ch + kb]);
            float4 iv1 = *reinterpret_cast<const float4*>(&ir1[128 * ch + kb]);
            const float* i0 = &iv0.x;
            const float* i1 = &iv1.x;
#pragma unroll
            for (int e = 0; e < 4; e++) {
                int k = kb + e;
                ulonglong2 wa = *reinterpret_cast<const ulonglong2*>(&W_s[k * 64 + 4 * tx]);
                ulonglong2 wb = *reinterpret_cast<const ulonglong2*>(&W_s[k * 64 + 32 + 4 * tx]);
                ull v0 = pk2(i0[e]);
                ull v1 = pk2(i1[e]);
                ffma2(acc[0][0], v0, wa.x); ffma2(acc[0][1], v0, wa.y);
                ffma2(acc[0][2], v0, wb.x); ffma2(acc[0][3], v0, wb.y);
                ffma2(acc[1][0], v1, wa.x); ffma2(acc[1][1], v1, wa.y);
                ffma2(acc[1][2], v1, wb.x); ffma2(acc[1][3], v1, wb.y);
            }
        }
    }

    // f1/f2 + tile pack staging
    float4 A1a = *reinterpret_cast<const float4*>(&a[4 * tx]);
    float4 A1b = *reinterpret_cast<const float4*>(&a[32 + 4 * tx]);
    float4 A2a = *reinterpret_cast<const float4*>(&a[OUTD + 4 * tx]);
    float4 A2b = *reinterpret_cast<const float4*>(&a[OUTD + 32 + 4 * tx]);

    // reuse smem: tile[32][65] + f2s[32] (2112 floats < 8192)
    float* tile = sm;
    float* f2s  = sm + 2112;
    __syncthreads();              // all W_s reads done

#pragma unroll
    for (int r = 0; r < 2; r++) {
        int lrow = 2 * rp + r;
        float2 p0 = upk(acc[r][0]), p1 = upk(acc[r][1]);
        float2 p2 = upk(acc[r][2]), p3 = upk(acc[r][3]);

        float* tr = &tile[lrow * 65];
        tr[4 * tx]     = p0.x; tr[4 * tx + 1] = p0.y;
        tr[4 * tx + 2] = p1.x; tr[4 * tx + 3] = p1.y;
        tr[32 + 4 * tx]     = p2.x; tr[32 + 4 * tx + 1] = p2.y;
        tr[32 + 4 * tx + 2] = p3.x; tr[32 + 4 * tx + 3] = p3.y;

        float s1 = p0.x * A1a.x + p0.y * A1a.y + p1.x * A1a.z + p1.y * A1a.w
                 + p2.x * A1b.x + p2.y * A1b.y + p3.x * A1b.z + p3.y * A1b.w;
        float s2 = p0.x * A2a.x + p0.y * A2a.y + p1.x * A2a.z + p1.y * A2a.w
                 + p2.x * A2b.x + p2.y * A2b.y + p3.x * A2b.z + p3.y * A2b.w;
#pragma unroll
        for (int off = 1; off < 8; off <<= 1) {
            s1 += __shfl_xor_sync(0xFFFFFFFFu, s1, off);
            s2 += __shfl_xor_sync(0xFFFFFFFFu, s2, off);
        }
        if (tx == 0) {
            int grow = rowBase + lrow;
            g_f1[grow]  = s1;
            g_f1L[grow] = s1 * L2E;
            g_f2[grow]  = s2;
            f2s[lrow]   = s2 * L2E;
            uint32_t u = __float_as_uint(s2);
            uint32_t key = u ^ (uint32_t)(((int)u >> 31) | 0x80000000);
            redmax(&g_maxkey, key);
        }
    }
    __syncthreads();

    // f2p (permuted): 8 items = 2 j16 groups x 4 fc
    if (t < 8) {
        int j16r = t >> 2, fc = t & 3;
        int j = j16r * 16 + 4 * fc;
        g_f2p[(b * 2 + j16r) * 4 + fc] =
            make_float4(f2s[j], f2s[j + 1], f2s[j + 2], f2s[j + 3]);
    }

    // pack B fragments (permuted, uint4 pairs q/q+4): 256 items, 2 per thread
#pragma unroll
    for (int m = 0; m < 2; m++) {
        int idx = t + 128 * m;        // 0..255 = j16r(2) x qq(4) x lane(32)
        int j16r = idx >> 7;
        int qq   = (idx >> 5) & 3;
        int lane = idx & 31;
        int fr = lane >> 2, fc = lane & 3;
        int j0 = j16r * 16 + 4 * fc;
        int n1 = qq * 8 + fr;
        int n2 = (qq + 4) * 8 + fr;
        __half2 lo1 = __floats2half2_rn(tile[j0 * 65 + n1],       tile[(j0 + 1) * 65 + n1]);
        __half2 hi1 = __floats2half2_rn(tile[(j0 + 2) * 65 + n1], tile[(j0 + 3) * 65 + n1]);
        __half2 lo2 = __floats2half2_rn(tile[j0 * 65 + n2],       tile[(j0 + 1) * 65 + n2]);
        __half2 hi2 = __floats2half2_rn(tile[(j0 + 2) * 65 + n2], tile[(j0 + 3) * 65 + n2]);
        uint4 pkt;
        pkt.x = *reinterpret_cast<uint32_t*>(&lo1);
        pkt.y = *reinterpret_cast<uint32_t*>(&hi1);
        pkt.z = *reinterpret_cast<uint32_t*>(&lo2);
        pkt.w = *reinterpret_cast<uint32_t*>(&hi2);
        g_hB4[((b * 2 + j16r) * 4 + qq) * 32 + lane] = pkt;
    }
}

// ---------------- launch 2: smem-B register-fragment attention (unchanged) ----------------
__global__ void __launch_bounds__(256, 3) k_attn(const int* __restrict__ adj) {
    __shared__ uint4  sB[2048];   // 32KB B fragments for this block's 256 j
    __shared__ float4 sF[64];     // 1KB  f2p

    int t = threadIdx.x;
    int wid = t >> 5, lane = t & 31;
    int fr = lane >> 2, fc = lane & 3;
    int mrow   = blockIdx.y * 128 + wid * 16;
    int jStart = blockIdx.x * JSPL;

    {
        const uint4* gB = g_hB4 + (size_t)(jStart / 16) * 128;
#pragma unroll
        for (int m = 0; m < 8; m++) sB[t + 256 * m] = gB[t + 256 * m];
        if (t < 64) sF[t] = g_f2p[(size_t)(jStart / 16) * 4 + t];
    }

    float mL;
    {
        uint32_t k = g_maxkey;
        uint32_t u = (k & 0x80000000u) ? (k ^ 0x80000000u) : ~k;
        mL = __uint_as_float(u) * L2E;
    }

    float f1L0 = g_f1L[mrow + fr];
    float f1L1 = g_f1L[mrow + fr + 8];
    float y0 = f1L0 + mL, y1 = f1L1 + mL;
    float ci0 = fmaxf(y0, 0.01f * y0);
    float ci1 = fmaxf(y1, 0.01f * y1);

    const int4* pr0 = reinterpret_cast<const int4*>(adj + (size_t)(mrow + fr) * N_ + jStart) + fc;
    const int4* pr1 = reinterpret_cast<const int4*>(adj + (size_t)(mrow + fr + 8) * N_ + jStart) + fc;

    float accv[8][4];
#pragma unroll
    for (int q = 0; q < 8; q++)
#pragma unroll
        for (int g = 0; g < 4; g++) accv[q][g] = 0.f;
    float accs[4] = {0.f, 0.f, 0.f, 0.f};

    const uint32_t bone = (fr == 0) ? 0x3C003C00u : 0u;

    int4 avA0 = __ldcs(pr0), avA1 = __ldcs(pr1);
    __syncthreads();

#define GEN_A(AREG, AVA, AVB, FV)                                                 \
    do {                                                                          \
        float e00, e01, e02, e03, e10, e11, e12, e13;                             \
        { float y = f1L0 + (FV).x; e00 = ex2f(fmaxf(y - ci0, fmaf(y, 0.01f, -ci0))); } \
        { float y = f1L0 + (FV).y; e01 = ex2f(fmaxf(y - ci0, fmaf(y, 0.01f, -ci0))); } \
        { float y = f1L0 + (FV).z; e02 = ex2f(fmaxf(y - ci0, fmaf(y, 0.01f, -ci0))); } \
        { float y = f1L0 + (FV).w; e03 = ex2f(fmaxf(y - ci0, fmaf(y, 0.01f, -ci0))); } \
        { float y = f1L1 + (FV).x; e10 = ex2f(fmaxf(y - ci1, fmaf(y, 0.01f, -ci1))); } \
        { float y = f1L1 + (FV).y; e11 = ex2f(fmaxf(y - ci1, fmaf(y, 0.01f, -ci1))); } \
        { float y = f1L1 + (FV).z; e12 = ex2f(fmaxf(y - ci1, fmaf(y, 0.01f, -ci1))); } \
        { float y = f1L1 + (FV).w; e13 = ex2f(fmaxf(y - ci1, fmaf(y, 0.01f, -ci1))); } \
        __half2 h0 = __floats2half2_rn(e00, e01);                                 \
        __half2 h1 = __floats2half2_rn(e10, e11);                                 \
        __half2 h2 = __floats2half2_rn(e02, e03);                                 \
        __half2 h3 = __floats2half2_rn(e12, e13);                                 \
        uint32_t mA0 = (uint32_t)(AVA).x * 0xFFFFu + (uint32_t)(AVA).y * 0xFFFF0000u; \
        uint32_t mA1 = (uint32_t)(AVA).z * 0xFFFFu + (uint32_t)(AVA).w * 0xFFFF0000u; \
        uint32_t mB0 = (uint32_t)(AVB).x * 0xFFFFu + (uint32_t)(AVB).y * 0xFFFF0000u; \
        uint32_t mB1 = (uint32_t)(AVB).z * 0xFFFFu + (uint32_t)(AVB).w * 0xFFFF0000u; \
        (AREG)[0] = *reinterpret_cast<uint32_t*>(&h0) & mA0;                      \
        (AREG)[1] = *reinterpret_cast<uint32_t*>(&h1) & mB0;                      \
        (AREG)[2] = *reinterpret_cast<uint32_t*>(&h2) & mA1;                      \
        (AREG)[3] = *reinterpret_cast<uint32_t*>(&h3) & mB1;                      \
    } while (0)

#pragma unroll 2
    for (int ch = 0; ch < CH; ch++) {
        int4 avB0 = __ldcs(pr0 + 4), avB1 = __ldcs(pr1 + 4);

        {
            uint4 bq[4];
#pragma unroll
            for (int qq = 0; qq < 4; qq++) bq[qq] = sB[ch * 256 + qq * 32 + lane];
            float4 fv = sF[ch * 8 + fc];
            uint32_t a[4];
            GEN_A(a, avA0, avA1, fv);
#pragma unroll
            for (int qq = 0; qq < 4; qq++) {
                mma16(accv[qq],     a, bq[qq].x, bq[qq].y);
                mma16(accv[qq + 4], a, bq[qq].z, bq[qq].w);
            }
            mma16(accs, a, bone, bone);
        }

        if (ch + 1 < CH) { avA0 = __ldcs(pr0 + 8); avA1 = __ldcs(pr1 + 8); }

        {
            uint4 bq[4];
#pragma unroll
            for (int qq = 0; qq < 4; qq++) bq[qq] = sB[ch * 256 + 128 + qq * 32 + lane];
            float4 fv = sF[ch * 8 + 4 + fc];
            uint32_t a[4];
            GEN_A(a, avB0, avB1, fv);
#pragma unroll
            for (int qq = 0; qq < 4; qq++) {
                mma16(accv[qq],     a, bq[qq].x, bq[qq].y);
                mma16(accv[qq + 4], a, bq[qq].z, bq[qq].w);
            }
            mma16(accs, a, bone, bone);
        }

        pr0 += 8; pr1 += 8;
    }
#undef GEN_A

#pragma unroll
    for (int q = 0; q < 8; q++) {
        int col = q * 8 + 2 * fc;
        red2(&g_V[(mrow + fr) * OUTD + col],     accv[q][0], accv[q][1]);
        red2(&g_V[(mrow + fr + 8) * OUTD + col], accv[q][2], accv[q][3]);
    }
    if (fc == 0) {
        red1(&g_S[mrow + fr],     accs[0]);
        red1(&g_S[mrow + fr + 8], accs[2]);
    }
}

// ---------------- launch 3: normalize + scalar outputs + state restore ----------------
__global__ void __launch_bounds__(256) k_fin(float* __restrict__ out) {
    int gid = blockIdx.x * blockDim.x + threadIdx.x;   // 0..131071 float4s
    float4 v = reinterpret_cast<const float4*>(g_V)[gid];
    float  s = g_S[gid >> 4];
    float  inv = 1.0f / s;
    reinterpret_cast<float4*>(out)[gid] =
        make_float4(v.x * inv, v.y * inv, v.z * inv, v.w * inv);
    reinterpret_cast<float4*>(g_V)[gid] = make_float4(0.f, 0.f, 0.f, 0.f);
    if (gid < 3) {
        float x;
        if (gid == 0)      x = g_f1[1] + g_f2[2];   // face_Rhand = e[1,2]
        else if (gid == 1) x = g_f1[1] + g_f2[3];   // face_Lhand = e[1,3]
        else               x = g_f1[3] + g_f2[2];   // Rhand_Lhand = e[3,2]
        out[N_ * OUTD + gid] = fmaxf(x, 0.01f * x);
    }
    if (gid == 4) g_maxkey = 0u;
}

// ---------------- launch ----------------
extern "C" void kernel_launch(void* const* d_in, const int* in_sizes, int n_in,
                              void* d_out, int out_size) {
    const float* input = (const float*)d_in[0];
    const int*   adj   = (const int*)  d_in[1];
    const float* W     = (const float*)d_in[2];
    const float* a     = (const float*)d_in[3];
    float*       out   = (float*)d_out;
    (void)in_sizes; (void)n_in; (void)out_size;

    cudaFuncSetAttribute(k_h, cudaFuncAttributeMaxDynamicSharedMemorySize, KH_SMEM);

    k_h   <<<256, 128, KH_SMEM>>>(input, W, a);
    k_attn<<<dim3(NS, N_ / 128), 256>>>(adj);
    k_fin <<<512, 256>>>(out);
}